// round 4
// baseline (speedup 1.0000x reference)
#include <cuda_runtime.h>

#define MAXN 65536
#define EPSF 1e-5f

// ---------------- scratch: float4-typed for guaranteed 16B alignment ---------
__device__ float4 g_U[MAXN * 32];     // X @ Wl
__device__ float4 g_V[MAXN * 32];     // X @ Wr
__device__ float4 g_agg[MAXN * 32];   // scatter accumulator
__device__ float4 g_H[MAXN * 32];     // pre-BN activations
__device__ float4 g_X[MAXN * 32];     // layer input ping buffer (layers >= 1)
__device__ float  g_deginv[MAXN];
__device__ float  g_deg[MAXN];
__device__ float  g_stats[256];       // [0:128) sum, [128:256) sumsq
__device__ int    g_is64;             // 1 if edge_index is int64, 0 if int32

__device__ __forceinline__ void fma4(float4& acc, float s, const float4& v) {
    acc.x = fmaf(s, v.x, acc.x);
    acc.y = fmaf(s, v.y, acc.y);
    acc.z = fmaf(s, v.z, acc.z);
    acc.w = fmaf(s, v.w, acc.w);
}

// Fetch edge endpoint (which=0 -> src row, which=1 -> dst row) honoring dtype.
__device__ __forceinline__ int edge_at(const void* ei, int which, int e, int E) {
    if (g_is64) {
        long long v = ((const long long*)ei)[(size_t)which * E + e];
        return (int)v;
    } else {
        return ((const int*)ei)[(size_t)which * E + e];
    }
}

// ---------------- dtype detection -------------------------------------------
__global__ void k_detect(const long long* __restrict__ ei, int N) {
    if (blockIdx.x == 0 && threadIdx.x == 0) {
        int ok = 1;
        for (int i = 0; i < 64; i++) {
            long long v = ei[i];
            if (v < 0 || v >= (long long)N) { ok = 0; break; }
        }
        g_is64 = ok;
    }
}

// ---------------- degree ------------------------------------------------------
__global__ void k_zero_deg(int N) {
    int i = blockIdx.x * blockDim.x + threadIdx.x;
    if (i < N) g_deg[i] = 0.f;
}

__global__ void k_deg(const void* __restrict__ ei, int E, int N) {
    int i = blockIdx.x * blockDim.x + threadIdx.x;
    if (i < E) {
        int d = edge_at(ei, 1, i, E);
        if ((unsigned)d < (unsigned)N) atomicAdd(&g_deg[d], 1.0f);
    }
}

__global__ void k_deginv(int N) {
    int i = blockIdx.x * blockDim.x + threadIdx.x;
    if (i < N) g_deginv[i] = 1.0f / fmaxf(g_deg[i], 1.0f);
}

// ---------------- per-layer zero (agg + stats) --------------------------------
__global__ void k_zero_layer(int n4) {
    int tid = blockIdx.x * blockDim.x + threadIdx.x;
    if (blockIdx.x == 0 && threadIdx.x < 256) g_stats[threadIdx.x] = 0.f;
    float4 z = make_float4(0.f, 0.f, 0.f, 0.f);
    for (int i = tid; i < n4; i += gridDim.x * blockDim.x)
        g_agg[i] = z;
}

// ---------------- fused dual GEMM: U = X@Wl, V = X@Wr --------------------------
// Block tile: 64 rows x 128 cols. 256 threads; thread (rg,cg) computes rows
// rg*4..rg*4+3 and column float4s {cg, cg+16}.
__global__ __launch_bounds__(256)
void k_gemm(const float4* __restrict__ Xext, int useExt,
            const float4* __restrict__ Wl4, const float4* __restrict__ Wr4, int N) {
    const float4* __restrict__ X = useExt ? Xext : g_X;
    __shared__ float  sX[64][33];     // [row][k within chunk], padded
    __shared__ float4 sWl[32][32];    // [k][col4]
    __shared__ float4 sWr[32][32];

    const int tid = threadIdx.x;
    const int rg = tid >> 4;          // 0..15
    const int cg = tid & 15;          // 0..15
    const int rowBase = blockIdx.x * 64;

    float4 aU[4][2], aV[4][2];
    const float4 z4 = make_float4(0.f, 0.f, 0.f, 0.f);
#pragma unroll
    for (int i = 0; i < 4; i++) {
        aU[i][0] = z4; aU[i][1] = z4; aV[i][0] = z4; aV[i][1] = z4;
    }

    for (int k0 = 0; k0 < 32; k0 += 8) {          // k0 in float4 units
        // stage X chunk: 64 rows x 8 float4 (= 32 k values)
#pragma unroll
        for (int t = 0; t < 2; t++) {
            int v = tid + t * 256;                // 0..511
            int r = v >> 3, q = v & 7;            // row 0..63, float4 idx 0..7
            int grow = rowBase + r;
            float4 xv = (grow < N) ? X[(size_t)grow * 32 + k0 + q] : z4;
            sX[r][q * 4 + 0] = xv.x;
            sX[r][q * 4 + 1] = xv.y;
            sX[r][q * 4 + 2] = xv.z;
            sX[r][q * 4 + 3] = xv.w;
        }
        // stage W chunks: 32 k-rows x 32 float4 cols each
#pragma unroll
        for (int t = 0; t < 4; t++) {
            int v = tid + t * 256;                // 0..1023
            int k = v >> 5, c = v & 31;
            sWl[k][c] = Wl4[(size_t)(k0 * 4 + k) * 32 + c];
            sWr[k][c] = Wr4[(size_t)(k0 * 4 + k) * 32 + c];
        }
        __syncthreads();

#pragma unroll 4
        for (int k = 0; k < 32; k++) {
            float a0 = sX[rg * 4 + 0][k];
            float a1 = sX[rg * 4 + 1][k];
            float a2 = sX[rg * 4 + 2][k];
            float a3 = sX[rg * 4 + 3][k];
            float4 wl0 = sWl[k][cg];
            float4 wl1 = sWl[k][cg + 16];
            float4 wr0 = sWr[k][cg];
            float4 wr1 = sWr[k][cg + 16];
            fma4(aU[0][0], a0, wl0); fma4(aU[0][1], a0, wl1);
            fma4(aU[1][0], a1, wl0); fma4(aU[1][1], a1, wl1);
            fma4(aU[2][0], a2, wl0); fma4(aU[2][1], a2, wl1);
            fma4(aU[3][0], a3, wl0); fma4(aU[3][1], a3, wl1);
            fma4(aV[0][0], a0, wr0); fma4(aV[0][1], a0, wr1);
            fma4(aV[1][0], a1, wr0); fma4(aV[1][1], a1, wr1);
            fma4(aV[2][0], a2, wr0); fma4(aV[2][1], a2, wr1);
            fma4(aV[3][0], a3, wr0); fma4(aV[3][1], a3, wr1);
        }
        __syncthreads();
    }

#pragma unroll
    for (int i = 0; i < 4; i++) {
        int grow = rowBase + rg * 4 + i;
        if (grow < N) {
            size_t base = (size_t)grow * 32;
            g_U[base + cg]      = aU[i][0];
            g_U[base + cg + 16] = aU[i][1];
            g_V[base + cg]      = aV[i][0];
            g_V[base + cg + 16] = aV[i][1];
        }
    }
}

// ---------------- scatter: agg[dst] += U[src], one warp per edge ---------------
__global__ void k_scatter(const void* __restrict__ ei, int E, int N) {
    int gw = (blockIdx.x * blockDim.x + threadIdx.x) >> 5;
    if (gw >= E) return;
    int lane = threadIdx.x & 31;
    int s = edge_at(ei, 0, gw, E);
    int d = edge_at(ei, 1, gw, E);
    if ((unsigned)s >= (unsigned)N || (unsigned)d >= (unsigned)N) return;
    float4 v = g_U[(size_t)s * 32 + lane];
    float* ap = (float*)g_agg + (size_t)d * 128 + lane * 4;
    atomicAdd(ap + 0, v.x);
    atomicAdd(ap + 1, v.y);
    atomicAdd(ap + 2, v.z);
    atomicAdd(ap + 3, v.w);
}

// ---------------- epilogue 1: H = agg*deginv + V + b; BN stats -----------------
__global__ void k_epi1(const float* __restrict__ b, int N) {
    __shared__ float s1[128], s2s[128];
    const float* __restrict__ agg = (const float*)g_agg;
    const float* __restrict__ V = (const float*)g_V;
    float* __restrict__ H = (float*)g_H;
    int col = threadIdx.x & 127;
    int rsub = threadIdx.x >> 7;      // 0 or 1
    float bc = b[col];
    float s = 0.f, s2 = 0.f;
    for (int row = blockIdx.x * 2 + rsub; row < N; row += gridDim.x * 2) {
        size_t idx = (size_t)row * 128 + col;
        float h = agg[idx] * g_deginv[row] + V[idx] + bc;
        H[idx] = h;
        s += h;
        s2 += h * h;
    }
    if (rsub == 1) { s1[col] = s; s2s[col] = s2; }
    __syncthreads();
    if (rsub == 0) {
        atomicAdd(&g_stats[col], s + s1[col]);
        atomicAdd(&g_stats[128 + col], s2 + s2s[col]);
    }
}

// ---------------- epilogue 2: BN normalize + ReLU -------------------------------
__global__ void k_epi2(const float* __restrict__ gamma, const float* __restrict__ beta,
                       float4* __restrict__ outExt, int useExt, int N, float invN) {
    __shared__ float sc[128], sh[128];
    if (threadIdx.x < 128) {
        int c = threadIdx.x;
        float mu = g_stats[c] * invN;
        float var = g_stats[128 + c] * invN - mu * mu;
        float s = gamma[c] * rsqrtf(var + EPSF);
        sc[c] = s;
        sh[c] = beta[c] - mu * s;
    }
    __syncthreads();
    float4* __restrict__ out = useExt ? outExt : g_X;
    int n4 = N * 32;
    for (int i = blockIdx.x * blockDim.x + threadIdx.x; i < n4;
         i += gridDim.x * blockDim.x) {
        int cq = (i & 31) * 4;
        float4 h = g_H[i];
        float4 o;
        o.x = fmaxf(fmaf(h.x, sc[cq + 0], sh[cq + 0]), 0.f);
        o.y = fmaxf(fmaf(h.y, sc[cq + 1], sh[cq + 1]), 0.f);
        o.z = fmaxf(fmaf(h.z, sc[cq + 2], sh[cq + 2]), 0.f);
        o.w = fmaxf(fmaf(h.w, sc[cq + 3], sh[cq + 3]), 0.f);
        out[i] = o;
    }
}

// ---------------- launch ---------------------------------------------------------
extern "C" void kernel_launch(void* const* d_in, const int* in_sizes, int n_in,
                              void* d_out, int out_size) {
    const float4* x = (const float4*)d_in[0];
    const void* ei = d_in[1];
    const float4* Wl = (const float4*)d_in[2];
    const float4* Wr = (const float4*)d_in[3];
    const float* b = (const float*)d_in[4];
    const float* gamma = (const float*)d_in[5];
    const float* beta = (const float*)d_in[6];

    int N = in_sizes[0] / 128;
    int E = in_sizes[1] / 2;
    int L = in_sizes[4] / 128;
    float4* out = (float4*)d_out;

    // dtype of edge_index (int64 vs int32), then degree (reused by every layer)
    k_detect<<<1, 32>>>((const long long*)ei, N);
    k_zero_deg<<<(N + 255) / 256, 256>>>(N);
    k_deg<<<(E + 255) / 256, 256>>>(ei, E, N);
    k_deginv<<<(N + 255) / 256, 256>>>(N);

    int gemmBlocks = (N + 63) / 64;
    long long swork = (long long)E * 32;
    int scatterBlocks = (int)((swork + 255) / 256);

    for (int l = 0; l < L; l++) {
        k_zero_layer<<<1024, 256>>>(N * 32);
        k_gemm<<<gemmBlocks, 256>>>(x, (l == 0) ? 1 : 0,
                                    Wl + (size_t)l * 4096, Wr + (size_t)l * 4096, N);
        k_scatter<<<scatterBlocks, 256>>>(ei, E, N);
        k_epi1<<<1184, 256>>>(b + (size_t)l * 128, N);
        k_epi2<<<1184, 256>>>(gamma + (size_t)l * 128, beta + (size_t)l * 128,
                              out, (l == L - 1) ? 1 : 0, N, 1.0f / (float)N);
    }
}

// round 5
// speedup vs baseline: 2.0061x; 2.0061x over previous
#include <cuda_runtime.h>

#define MAXN 65536
#define MAXE 2097152
#define EPSF 1e-5f

// ---------------- scratch ------------------------------------------------------
__device__ float4 g_U[MAXN * 32];     // X @ Wl
__device__ float4 g_V[MAXN * 32];     // X @ Wr
__device__ float4 g_H[MAXN * 32];     // pre-BN activations
__device__ float4 g_X[MAXN * 32];     // layer input ping buffer (layers >= 1)
__device__ float  g_stats[256];       // [0:128) sum, [128:256) sumsq
__device__ int    g_is64;             // 1 if edge_index is int64, 0 if int32
__device__ int    g_cnt[MAXN];        // histogram / fill cursor
__device__ int    g_rowptr[MAXN + 1];
__device__ int    g_colidx[MAXE];     // src node per edge, grouped by dst

// Fetch edge endpoint (which=0 -> src, which=1 -> dst) honoring dtype.
__device__ __forceinline__ int edge_at(const void* ei, int which, int e, int E) {
    if (g_is64) return (int)((const long long*)ei)[(size_t)which * E + e];
    return ((const int*)ei)[(size_t)which * E + e];
}

__device__ __forceinline__ void fma4(float4& acc, float s, const float4& v) {
    acc.x = fmaf(s, v.x, acc.x);
    acc.y = fmaf(s, v.y, acc.y);
    acc.z = fmaf(s, v.z, acc.z);
    acc.w = fmaf(s, v.w, acc.w);
}
__device__ __forceinline__ void add4(float4& a, const float4& b) {
    a.x += b.x; a.y += b.y; a.z += b.z; a.w += b.w;
}

// ---------------- dtype detection ----------------------------------------------
__global__ void k_detect(const long long* __restrict__ ei, int N) {
    if (threadIdx.x == 0) {
        int ok = 1;
        for (int i = 0; i < 64; i++) {
            long long v = ei[i];
            if (v < 0 || v >= (long long)N) { ok = 0; break; }
        }
        g_is64 = ok;
    }
}

// ---------------- CSR build -----------------------------------------------------
__global__ void k_zero_cnt(int N) {
    int i = blockIdx.x * blockDim.x + threadIdx.x;
    if (i < N) g_cnt[i] = 0;
}

__global__ void k_hist(const void* __restrict__ ei, int E, int N) {
    int i = blockIdx.x * blockDim.x + threadIdx.x;
    if (i < E) {
        int d = edge_at(ei, 1, i, E);
        if ((unsigned)d < (unsigned)N) atomicAdd(&g_cnt[d], 1);
    }
}

// single-block exclusive scan of g_cnt[0..N) -> g_rowptr[0..N]
__global__ void k_scan(int N) {
    __shared__ int warp_sums[32];
    __shared__ int s_carry;
    int lane = threadIdx.x & 31, wid = threadIdx.x >> 5;
    if (threadIdx.x == 0) { s_carry = 0; g_rowptr[0] = 0; }
    __syncthreads();
    for (int base = 0; base < N; base += 1024) {
        int i = base + threadIdx.x;
        int x = (i < N) ? g_cnt[i] : 0;
#pragma unroll
        for (int o = 1; o < 32; o <<= 1) {
            int y = __shfl_up_sync(0xffffffffu, x, o);
            if (lane >= o) x += y;
        }
        if (lane == 31) warp_sums[wid] = x;
        __syncthreads();
        if (wid == 0) {
            int w = warp_sums[lane];
#pragma unroll
            for (int o = 1; o < 32; o <<= 1) {
                int y = __shfl_up_sync(0xffffffffu, w, o);
                if (lane >= o) w += y;
            }
            warp_sums[lane] = w;
        }
        __syncthreads();
        int incl = x + (wid > 0 ? warp_sums[wid - 1] : 0) + s_carry;
        if (i < N) g_rowptr[i + 1] = incl;
        __syncthreads();
        if (threadIdx.x == 0) s_carry += warp_sums[31];
        __syncthreads();
    }
}

__global__ void k_fill(const void* __restrict__ ei, int E, int N) {
    int i = blockIdx.x * blockDim.x + threadIdx.x;
    if (i < E) {
        int s = edge_at(ei, 0, i, E);
        int d = edge_at(ei, 1, i, E);
        if ((unsigned)s >= (unsigned)N || (unsigned)d >= (unsigned)N) return;
        int pos = g_rowptr[d] + atomicAdd(&g_cnt[d], 1);
        if (pos < MAXE) g_colidx[pos] = s;
    }
}

// ---------------- per-layer stats zero -------------------------------------------
__global__ void k_zero_stats() {
    g_stats[threadIdx.x] = 0.f;
}

// ---------------- fused dual GEMM: U = X@Wl, V = X@Wr -----------------------------
__global__ __launch_bounds__(256)
void k_gemm(const float4* __restrict__ Xext, int useExt,
            const float4* __restrict__ Wl4, const float4* __restrict__ Wr4, int N) {
    const float4* __restrict__ X = useExt ? Xext : g_X;
    __shared__ float  sX[64][33];
    __shared__ float4 sWl[32][32];
    __shared__ float4 sWr[32][32];

    const int tid = threadIdx.x;
    const int rg = tid >> 4;
    const int cg = tid & 15;
    const int rowBase = blockIdx.x * 64;

    float4 aU[4][2], aV[4][2];
    const float4 z4 = make_float4(0.f, 0.f, 0.f, 0.f);
#pragma unroll
    for (int i = 0; i < 4; i++) {
        aU[i][0] = z4; aU[i][1] = z4; aV[i][0] = z4; aV[i][1] = z4;
    }

    for (int k0 = 0; k0 < 32; k0 += 8) {
#pragma unroll
        for (int t = 0; t < 2; t++) {
            int v = tid + t * 256;
            int r = v >> 3, q = v & 7;
            int grow = rowBase + r;
            float4 xv = (grow < N) ? X[(size_t)grow * 32 + k0 + q] : z4;
            sX[r][q * 4 + 0] = xv.x;
            sX[r][q * 4 + 1] = xv.y;
            sX[r][q * 4 + 2] = xv.z;
            sX[r][q * 4 + 3] = xv.w;
        }
#pragma unroll
        for (int t = 0; t < 4; t++) {
            int v = tid + t * 256;
            int k = v >> 5, c = v & 31;
            sWl[k][c] = Wl4[(size_t)(k0 * 4 + k) * 32 + c];
            sWr[k][c] = Wr4[(size_t)(k0 * 4 + k) * 32 + c];
        }
        __syncthreads();

#pragma unroll 4
        for (int k = 0; k < 32; k++) {
            float a0 = sX[rg * 4 + 0][k];
            float a1 = sX[rg * 4 + 1][k];
            float a2 = sX[rg * 4 + 2][k];
            float a3 = sX[rg * 4 + 3][k];
            float4 wl0 = sWl[k][cg];
            float4 wl1 = sWl[k][cg + 16];
            float4 wr0 = sWr[k][cg];
            float4 wr1 = sWr[k][cg + 16];
            fma4(aU[0][0], a0, wl0); fma4(aU[0][1], a0, wl1);
            fma4(aU[1][0], a1, wl0); fma4(aU[1][1], a1, wl1);
            fma4(aU[2][0], a2, wl0); fma4(aU[2][1], a2, wl1);
            fma4(aU[3][0], a3, wl0); fma4(aU[3][1], a3, wl1);
            fma4(aV[0][0], a0, wr0); fma4(aV[0][1], a0, wr1);
            fma4(aV[1][0], a1, wr0); fma4(aV[1][1], a1, wr1);
            fma4(aV[2][0], a2, wr0); fma4(aV[2][1], a2, wr1);
            fma4(aV[3][0], a3, wr0); fma4(aV[3][1], a3, wr1);
        }
        __syncthreads();
    }

#pragma unroll
    for (int i = 0; i < 4; i++) {
        int grow = rowBase + rg * 4 + i;
        if (grow < N) {
            size_t base = (size_t)grow * 32;
            g_U[base + cg]      = aU[i][0];
            g_U[base + cg + 16] = aU[i][1];
            g_V[base + cg]      = aV[i][0];
            g_V[base + cg + 16] = aV[i][1];
        }
    }
}

// ---------------- fused gather-mean + bias + BN-stats -----------------------------
// One warp per dst node: acc = sum_{e in row} U[col[e]]; H = acc/deg + V + b.
// BN stats accumulated per-warp (registers) -> shared -> global atomics.
__global__ __launch_bounds__(256)
void k_aggr(const float4* __restrict__ b4, int N) {
    __shared__ float sS[256];     // [0:128) sum, [128:256) sumsq
    if (threadIdx.x < 256) sS[threadIdx.x] = 0.f;
    __syncthreads();

    const int lane = threadIdx.x & 31;
    const int warpsPerBlock = blockDim.x >> 5;
    const int gwarp = blockIdx.x * warpsPerBlock + (threadIdx.x >> 5);
    const int nWarps = gridDim.x * warpsPerBlock;

    const float4 z4 = make_float4(0.f, 0.f, 0.f, 0.f);
    float4 wSum = z4, wSq = z4;
    const float4 bv = b4[lane];

    for (int node = gwarp; node < N; node += nWarps) {
        int beg = g_rowptr[node];
        int end = g_rowptr[node + 1];
        float4 acc0 = z4, acc1 = z4;
        int e = beg;
        for (; e + 1 < end; e += 2) {
            int s0 = g_colidx[e];
            int s1 = g_colidx[e + 1];
            float4 u0 = g_U[(size_t)s0 * 32 + lane];
            float4 u1 = g_U[(size_t)s1 * 32 + lane];
            add4(acc0, u0);
            add4(acc1, u1);
        }
        if (e < end) add4(acc0, g_U[(size_t)g_colidx[e] * 32 + lane]);
        add4(acc0, acc1);

        float di = 1.0f / fmaxf((float)(end - beg), 1.0f);
        float4 v = g_V[(size_t)node * 32 + lane];
        float4 h;
        h.x = fmaf(acc0.x, di, v.x) + bv.x;
        h.y = fmaf(acc0.y, di, v.y) + bv.y;
        h.z = fmaf(acc0.z, di, v.z) + bv.z;
        h.w = fmaf(acc0.w, di, v.w) + bv.w;
        g_H[(size_t)node * 32 + lane] = h;

        add4(wSum, h);
        wSq.x = fmaf(h.x, h.x, wSq.x);
        wSq.y = fmaf(h.y, h.y, wSq.y);
        wSq.z = fmaf(h.z, h.z, wSq.z);
        wSq.w = fmaf(h.w, h.w, wSq.w);
    }

    // warp -> shared
    int c = lane * 4;
    atomicAdd(&sS[c + 0], wSum.x);
    atomicAdd(&sS[c + 1], wSum.y);
    atomicAdd(&sS[c + 2], wSum.z);
    atomicAdd(&sS[c + 3], wSum.w);
    atomicAdd(&sS[128 + c + 0], wSq.x);
    atomicAdd(&sS[128 + c + 1], wSq.y);
    atomicAdd(&sS[128 + c + 2], wSq.z);
    atomicAdd(&sS[128 + c + 3], wSq.w);
    __syncthreads();
    if (threadIdx.x < 256) atomicAdd(&g_stats[threadIdx.x], sS[threadIdx.x]);
}

// ---------------- BN normalize + ReLU ---------------------------------------------
__global__ void k_epi2(const float* __restrict__ gamma, const float* __restrict__ beta,
                       float4* __restrict__ outExt, int useExt, int N, float invN) {
    __shared__ float sc[128], sh[128];
    if (threadIdx.x < 128) {
        int c = threadIdx.x;
        float mu = g_stats[c] * invN;
        float var = g_stats[128 + c] * invN - mu * mu;
        float s = gamma[c] * rsqrtf(var + EPSF);
        sc[c] = s;
        sh[c] = beta[c] - mu * s;
    }
    __syncthreads();
    float4* __restrict__ out = useExt ? outExt : g_X;
    int n4 = N * 32;
    for (int i = blockIdx.x * blockDim.x + threadIdx.x; i < n4;
         i += gridDim.x * blockDim.x) {
        int cq = (i & 31) * 4;
        float4 h = g_H[i];
        float4 o;
        o.x = fmaxf(fmaf(h.x, sc[cq + 0], sh[cq + 0]), 0.f);
        o.y = fmaxf(fmaf(h.y, sc[cq + 1], sh[cq + 1]), 0.f);
        o.z = fmaxf(fmaf(h.z, sc[cq + 2], sh[cq + 2]), 0.f);
        o.w = fmaxf(fmaf(h.w, sc[cq + 3], sh[cq + 3]), 0.f);
        out[i] = o;
    }
}

// ---------------- launch -------------------------------------------------------------
extern "C" void kernel_launch(void* const* d_in, const int* in_sizes, int n_in,
                              void* d_out, int out_size) {
    const float4* x = (const float4*)d_in[0];
    const void* ei = d_in[1];
    const float4* Wl = (const float4*)d_in[2];
    const float4* Wr = (const float4*)d_in[3];
    const float* b = (const float*)d_in[4];
    const float* gamma = (const float*)d_in[5];
    const float* beta = (const float*)d_in[6];

    int N = in_sizes[0] / 128;
    int E = in_sizes[1] / 2;
    int L = in_sizes[4] / 128;
    float4* out = (float4*)d_out;

    int eb = (E + 255) / 256;
    int nb = (N + 255) / 256;

    // dtype detect + CSR build (once per launch)
    k_detect<<<1, 32>>>((const long long*)ei, N);
    k_zero_cnt<<<nb, 256>>>(N);
    k_hist<<<eb, 256>>>(ei, E, N);
    k_scan<<<1, 1024>>>(N);
    k_zero_cnt<<<nb, 256>>>(N);
    k_fill<<<eb, 256>>>(ei, E, N);

    int gemmBlocks = (N + 63) / 64;

    for (int l = 0; l < L; l++) {
        k_zero_stats<<<1, 256>>>();
        k_gemm<<<gemmBlocks, 256>>>(x, (l == 0) ? 1 : 0,
                                    Wl + (size_t)l * 4096, Wr + (size_t)l * 4096, N);
        k_aggr<<<1184, 256>>>((const float4*)b + (size_t)l * 32, N);
        k_epi2<<<1184, 256>>>(gamma + (size_t)l * 128, beta + (size_t)l * 128,
                              out, (l == L - 1) ? 1 : 0, N, 1.0f / (float)N);
    }
}

// round 6
// speedup vs baseline: 2.0272x; 1.0105x over previous
#include <cuda_runtime.h>

#define MAXN 65536
#define MAXE 2097152
#define EPSF 1e-5f

// ---------------- scratch ------------------------------------------------------
__device__ float4 g_U[MAXN * 32];     // X @ Wl
__device__ float4 g_V[MAXN * 32];     // X @ Wr
__device__ float4 g_H[MAXN * 32];     // pre-BN activations (per layer)
__device__ float  g_stats[256];       // [0:128) sum, [128:256) sumsq
__device__ float  g_scale[128];       // BN scale  (gamma * rsqrt(var+eps))
__device__ float  g_shift[128];       // BN shift  (beta - mu*scale)
__device__ int    g_is64;             // 1 if edge_index is int64, 0 if int32
__device__ int    g_cnt[MAXN];        // histogram / fill cursor
__device__ int    g_rowptr[MAXN + 1];
__device__ int    g_colidx[MAXE];     // src node per edge, grouped by dst

__device__ __forceinline__ int edge_at(const void* ei, int which, int e, int E) {
    if (g_is64) return (int)((const long long*)ei)[(size_t)which * E + e];
    return ((const int*)ei)[(size_t)which * E + e];
}

__device__ __forceinline__ void fma4(float4& acc, float s, const float4& v) {
    acc.x = fmaf(s, v.x, acc.x);
    acc.y = fmaf(s, v.y, acc.y);
    acc.z = fmaf(s, v.z, acc.z);
    acc.w = fmaf(s, v.w, acc.w);
}
__device__ __forceinline__ void add4(float4& a, const float4& b) {
    a.x += b.x; a.y += b.y; a.z += b.z; a.w += b.w;
}

// ---------------- dtype detection ----------------------------------------------
__global__ void k_detect(const long long* __restrict__ ei, int N) {
    if (threadIdx.x == 0) {
        int ok = 1;
        for (int i = 0; i < 64; i++) {
            long long v = ei[i];
            if (v < 0 || v >= (long long)N) { ok = 0; break; }
        }
        g_is64 = ok;
    }
}

// ---------------- CSR build ------------------------------------------------------
__global__ void k_zero_cnt(int N) {
    int i = blockIdx.x * blockDim.x + threadIdx.x;
    if (i < N) g_cnt[i] = 0;
}

__global__ void k_hist(const void* __restrict__ ei, int E, int N) {
    int i = blockIdx.x * blockDim.x + threadIdx.x;
    if (i < E) {
        int d = edge_at(ei, 1, i, E);
        if ((unsigned)d < (unsigned)N) atomicAdd(&g_cnt[d], 1);
    }
}

// single-block scan: thread-serial chunks + block scan of totals
__global__ __launch_bounds__(1024)
void k_scan(int N) {
    __shared__ int warp_sums[32];
    const int tid = threadIdx.x;
    const int lane = tid & 31, wid = tid >> 5;
    int chunk = (N + 1023) >> 10;
    int beg = tid * chunk; if (beg > N) beg = N;
    int end = beg + chunk; if (end > N) end = N;

    int s = 0;
    for (int i = beg; i < end; i++) s += g_cnt[i];

    int x = s;
#pragma unroll
    for (int o = 1; o < 32; o <<= 1) {
        int y = __shfl_up_sync(0xffffffffu, x, o);
        if (lane >= o) x += y;
    }
    if (lane == 31) warp_sums[wid] = x;
    __syncthreads();
    if (wid == 0) {
        int w = warp_sums[lane];
#pragma unroll
        for (int o = 1; o < 32; o <<= 1) {
            int y = __shfl_up_sync(0xffffffffu, w, o);
            if (lane >= o) w += y;
        }
        warp_sums[lane] = w;
    }
    __syncthreads();
    int excl = x - s + (wid > 0 ? warp_sums[wid - 1] : 0);

    int run = excl;
    for (int i = beg; i < end; i++) {
        g_rowptr[i] = run;
        run += g_cnt[i];
    }
    if (tid == 0) g_rowptr[N] = warp_sums[31];
}

__global__ void k_fill(const void* __restrict__ ei, int E, int N) {
    int i = blockIdx.x * blockDim.x + threadIdx.x;
    if (i < E) {
        int s = edge_at(ei, 0, i, E);
        int d = edge_at(ei, 1, i, E);
        if ((unsigned)s >= (unsigned)N || (unsigned)d >= (unsigned)N) return;
        int pos = g_rowptr[d] + atomicAdd(&g_cnt[d], 1);
        if (pos < MAXE) g_colidx[pos] = s;
    }
}

// ---------------- stats zero / finalize ---------------------------------------------
__global__ void k_zero_stats() {
    g_stats[threadIdx.x] = 0.f;
}

// stats -> (scale, shift), then zero stats for the next layer
__global__ void k_finstats(const float* __restrict__ gamma,
                           const float* __restrict__ beta, float invN) {
    int c = threadIdx.x;          // 128 threads
    float mu = g_stats[c] * invN;
    float var = g_stats[128 + c] * invN - mu * mu;
    float s = gamma[c] * rsqrtf(var + EPSF);
    g_scale[c] = s;
    g_shift[c] = beta[c] - mu * s;
    g_stats[c] = 0.f;
    g_stats[128 + c] = 0.f;
}

// ---------------- fused dual GEMM: U = act(X)@Wl, V = act(X)@Wr ----------------------
// applyBN: X := relu(H*scale + shift) applied while staging (each element read once).
__global__ __launch_bounds__(256)
void k_gemm(const float4* __restrict__ Xext, int applyBN,
            const float4* __restrict__ Wl4, const float4* __restrict__ Wr4, int N) {
    const float4* __restrict__ X = applyBN ? g_H : Xext;
    __shared__ float  sX[64][33];
    __shared__ float4 sWl[32][32];
    __shared__ float4 sWr[32][32];
    __shared__ float  s_sc[128], s_sh[128];

    const int tid = threadIdx.x;
    const int rg = tid >> 4;
    const int cg = tid & 15;
    const int rowBase = blockIdx.x * 64;

    if (applyBN) {
        if (tid < 128) { s_sc[tid] = g_scale[tid]; s_sh[tid] = g_shift[tid]; }
        __syncthreads();
    }

    float4 aU[4][2], aV[4][2];
    const float4 z4 = make_float4(0.f, 0.f, 0.f, 0.f);
#pragma unroll
    for (int i = 0; i < 4; i++) {
        aU[i][0] = z4; aU[i][1] = z4; aV[i][0] = z4; aV[i][1] = z4;
    }

    for (int k0 = 0; k0 < 32; k0 += 8) {
#pragma unroll
        for (int t = 0; t < 2; t++) {
            int v = tid + t * 256;
            int r = v >> 3, q = v & 7;
            int grow = rowBase + r;
            float4 xv = z4;
            if (grow < N) {
                xv = X[(size_t)grow * 32 + k0 + q];
                if (applyBN) {
                    int cb = (k0 + q) * 4;
                    xv.x = fmaxf(fmaf(xv.x, s_sc[cb + 0], s_sh[cb + 0]), 0.f);
                    xv.y = fmaxf(fmaf(xv.y, s_sc[cb + 1], s_sh[cb + 1]), 0.f);
                    xv.z = fmaxf(fmaf(xv.z, s_sc[cb + 2], s_sh[cb + 2]), 0.f);
                    xv.w = fmaxf(fmaf(xv.w, s_sc[cb + 3], s_sh[cb + 3]), 0.f);
                }
            }
            sX[r][q * 4 + 0] = xv.x;
            sX[r][q * 4 + 1] = xv.y;
            sX[r][q * 4 + 2] = xv.z;
            sX[r][q * 4 + 3] = xv.w;
        }
#pragma unroll
        for (int t = 0; t < 4; t++) {
            int v = tid + t * 256;
            int k = v >> 5, c = v & 31;
            sWl[k][c] = Wl4[(size_t)(k0 * 4 + k) * 32 + c];
            sWr[k][c] = Wr4[(size_t)(k0 * 4 + k) * 32 + c];
        }
        __syncthreads();

#pragma unroll 4
        for (int k = 0; k < 32; k++) {
            float a0 = sX[rg * 4 + 0][k];
            float a1 = sX[rg * 4 + 1][k];
            float a2 = sX[rg * 4 + 2][k];
            float a3 = sX[rg * 4 + 3][k];
            float4 wl0 = sWl[k][cg];
            float4 wl1 = sWl[k][cg + 16];
            float4 wr0 = sWr[k][cg];
            float4 wr1 = sWr[k][cg + 16];
            fma4(aU[0][0], a0, wl0); fma4(aU[0][1], a0, wl1);
            fma4(aU[1][0], a1, wl0); fma4(aU[1][1], a1, wl1);
            fma4(aU[2][0], a2, wl0); fma4(aU[2][1], a2, wl1);
            fma4(aU[3][0], a3, wl0); fma4(aU[3][1], a3, wl1);
            fma4(aV[0][0], a0, wr0); fma4(aV[0][1], a0, wr1);
            fma4(aV[1][0], a1, wr0); fma4(aV[1][1], a1, wr1);
            fma4(aV[2][0], a2, wr0); fma4(aV[2][1], a2, wr1);
            fma4(aV[3][0], a3, wr0); fma4(aV[3][1], a3, wr1);
        }
        __syncthreads();
    }

#pragma unroll
    for (int i = 0; i < 4; i++) {
        int grow = rowBase + rg * 4 + i;
        if (grow < N) {
            size_t base = (size_t)grow * 32;
            g_U[base + cg]      = aU[i][0];
            g_U[base + cg + 16] = aU[i][1];
            g_V[base + cg]      = aV[i][0];
            g_V[base + cg + 16] = aV[i][1];
        }
    }
}

// ---------------- fused gather-mean + bias + BN-stats --------------------------------
__global__ __launch_bounds__(256)
void k_aggr(const float4* __restrict__ b4, int N) {
    __shared__ float sS[256];
    if (threadIdx.x < 256) sS[threadIdx.x] = 0.f;
    __syncthreads();

    const int lane = threadIdx.x & 31;
    const int warpsPerBlock = blockDim.x >> 5;
    const int gwarp = blockIdx.x * warpsPerBlock + (threadIdx.x >> 5);
    const int nWarps = gridDim.x * warpsPerBlock;

    const float4 z4 = make_float4(0.f, 0.f, 0.f, 0.f);
    float4 wSum = z4, wSq = z4;
    const float4 bv = b4[lane];

    for (int node = gwarp; node < N; node += nWarps) {
        int beg = g_rowptr[node];
        int end = g_rowptr[node + 1];
        float4 acc0 = z4, acc1 = z4;
        int e = beg;
        for (; e + 1 < end; e += 2) {
            int s0 = g_colidx[e];
            int s1 = g_colidx[e + 1];
            float4 u0 = g_U[(size_t)s0 * 32 + lane];
            float4 u1 = g_U[(size_t)s1 * 32 + lane];
            add4(acc0, u0);
            add4(acc1, u1);
        }
        if (e < end) add4(acc0, g_U[(size_t)g_colidx[e] * 32 + lane]);
        add4(acc0, acc1);

        float di = 1.0f / fmaxf((float)(end - beg), 1.0f);
        float4 v = g_V[(size_t)node * 32 + lane];
        float4 h;
        h.x = fmaf(acc0.x, di, v.x) + bv.x;
        h.y = fmaf(acc0.y, di, v.y) + bv.y;
        h.z = fmaf(acc0.z, di, v.z) + bv.z;
        h.w = fmaf(acc0.w, di, v.w) + bv.w;
        g_H[(size_t)node * 32 + lane] = h;

        add4(wSum, h);
        wSq.x = fmaf(h.x, h.x, wSq.x);
        wSq.y = fmaf(h.y, h.y, wSq.y);
        wSq.z = fmaf(h.z, h.z, wSq.z);
        wSq.w = fmaf(h.w, h.w, wSq.w);
    }

    int c = lane * 4;
    atomicAdd(&sS[c + 0], wSum.x);
    atomicAdd(&sS[c + 1], wSum.y);
    atomicAdd(&sS[c + 2], wSum.z);
    atomicAdd(&sS[c + 3], wSum.w);
    atomicAdd(&sS[128 + c + 0], wSq.x);
    atomicAdd(&sS[128 + c + 1], wSq.y);
    atomicAdd(&sS[128 + c + 2], wSq.z);
    atomicAdd(&sS[128 + c + 3], wSq.w);
    __syncthreads();
    if (threadIdx.x < 256) atomicAdd(&g_stats[threadIdx.x], sS[threadIdx.x]);
}

// ---------------- final BN normalize + ReLU (last layer only) -------------------------
__global__ void k_epi2(float4* __restrict__ out, int N) {
    __shared__ float sc[128], sh[128];
    if (threadIdx.x < 128) {
        sc[threadIdx.x] = g_scale[threadIdx.x];
        sh[threadIdx.x] = g_shift[threadIdx.x];
    }
    __syncthreads();
    int n4 = N * 32;
    for (int i = blockIdx.x * blockDim.x + threadIdx.x; i < n4;
         i += gridDim.x * blockDim.x) {
        int cq = (i & 31) * 4;
        float4 h = g_H[i];
        float4 o;
        o.x = fmaxf(fmaf(h.x, sc[cq + 0], sh[cq + 0]), 0.f);
        o.y = fmaxf(fmaf(h.y, sc[cq + 1], sh[cq + 1]), 0.f);
        o.z = fmaxf(fmaf(h.z, sc[cq + 2], sh[cq + 2]), 0.f);
        o.w = fmaxf(fmaf(h.w, sc[cq + 3], sh[cq + 3]), 0.f);
        out[i] = o;
    }
}

// ---------------- launch ----------------------------------------------------------------
extern "C" void kernel_launch(void* const* d_in, const int* in_sizes, int n_in,
                              void* d_out, int out_size) {
    const float4* x = (const float4*)d_in[0];
    const void* ei = d_in[1];
    const float4* Wl = (const float4*)d_in[2];
    const float4* Wr = (const float4*)d_in[3];
    const float* b = (const float*)d_in[4];
    const float* gamma = (const float*)d_in[5];
    const float* beta = (const float*)d_in[6];

    int N = in_sizes[0] / 128;
    int E = in_sizes[1] / 2;
    int L = in_sizes[4] / 128;
    float4* out = (float4*)d_out;
    float invN = 1.0f / (float)N;

    int eb = (E + 255) / 256;
    int nb = (N + 255) / 256;

    // dtype detect + CSR build (once per launch)
    k_detect<<<1, 32>>>((const long long*)ei, N);
    k_zero_cnt<<<nb, 256>>>(N);
    k_hist<<<eb, 256>>>(ei, E, N);
    k_scan<<<1, 1024>>>(N);
    k_zero_cnt<<<nb, 256>>>(N);
    k_fill<<<eb, 256>>>(ei, E, N);
    k_zero_stats<<<1, 256>>>();

    int gemmBlocks = (N + 63) / 64;

    for (int l = 0; l < L; l++) {
        k_gemm<<<gemmBlocks, 256>>>(x, (l == 0) ? 0 : 1,
                                    Wl + (size_t)l * 4096, Wr + (size_t)l * 4096, N);
        k_aggr<<<1184, 256>>>((const float4*)b + (size_t)l * 32, N);
        k_finstats<<<1, 128>>>(gamma + (size_t)l * 128, beta + (size_t)l * 128, invN);
    }
    k_epi2<<<1184, 256>>>(out, N);
}

// round 8
// speedup vs baseline: 2.3418x; 1.1552x over previous
#include <cuda_runtime.h>
#include <cuda_fp16.h>
#include <cstdint>

#define MAXN 65536
#define MAXE 2097152
#define EPSF 1e-5f

// ================= scratch =================
__device__ uint2  g_Uh[MAXN * 32];    // act(X) @ Wl, fp16 (4 halves per uint2; idx j = cols 4j..4j+3)
__device__ float4 g_V[MAXN * 32];     // act(X) @ Wr, fp32
__device__ float4 g_H[MAXN * 32];     // pre-BN activations
__device__ float  g_stats[256];
__device__ float  g_scale[128];
__device__ float  g_shift[128];
__device__ int    g_is64;
__device__ int    g_cnt[MAXN];
__device__ int    g_rowptr[MAXN + 1];
__device__ int    g_colidx[MAXE];
__device__ int    g_btot[64];
__device__ int    g_boff[64];

__device__ __forceinline__ int edge_at(const void* ei, int which, int e, int E) {
    if (g_is64) return (int)((const long long*)ei)[(size_t)which * E + e];
    return ((const int*)ei)[(size_t)which * E + e];
}
__device__ __forceinline__ void fma4(float4& acc, float s, const float4& v) {
    acc.x = fmaf(s, v.x, acc.x);
    acc.y = fmaf(s, v.y, acc.y);
    acc.z = fmaf(s, v.z, acc.z);
    acc.w = fmaf(s, v.w, acc.w);
}
__device__ __forceinline__ void add4(float4& a, const float4& b) {
    a.x += b.x; a.y += b.y; a.z += b.z; a.w += b.w;
}
__device__ __forceinline__ void addh4(float4& a, const uint2& u) {
    float2 lo = __half22float2(*reinterpret_cast<const __half2*>(&u.x));
    float2 hi = __half22float2(*reinterpret_cast<const __half2*>(&u.y));
    a.x += lo.x; a.y += lo.y; a.z += hi.x; a.w += hi.y;
}
__device__ __forceinline__ uint2 pack_h4(const float4& v) {
    uint2 r;
    __half2 lo = __floats2half2_rn(v.x, v.y);
    __half2 hi = __floats2half2_rn(v.z, v.w);
    r.x = *reinterpret_cast<unsigned*>(&lo);
    r.y = *reinterpret_cast<unsigned*>(&hi);
    return r;
}

// ================= dtype detect =================
__global__ void k_detect(const long long* __restrict__ ei, int N) {
    if (threadIdx.x == 0) {
        int ok = 1;
        for (int i = 0; i < 64; i++) {
            long long v = ei[i];
            if (v < 0 || v >= (long long)N) { ok = 0; break; }
        }
        g_is64 = ok;
    }
}

// ================= CSR build =================
__global__ void k_zero_cnt(int N) {
    int i = blockIdx.x * blockDim.x + threadIdx.x;
    if (i < N) g_cnt[i] = 0;
}
__global__ void k_hist(const void* __restrict__ ei, int E, int N) {
    int i = blockIdx.x * blockDim.x + threadIdx.x;
    if (i < E) {
        int d = edge_at(ei, 1, i, E);
        if ((unsigned)d < (unsigned)N) atomicAdd(&g_cnt[d], 1);
    }
}

// 3-phase multi-block exclusive scan
__global__ __launch_bounds__(1024)
void k_scan1(int N) {
    __shared__ int wsum[32];
    int i = blockIdx.x * 1024 + threadIdx.x;
    int lane = threadIdx.x & 31, wid = threadIdx.x >> 5;
    int v = (i < N) ? g_cnt[i] : 0;
    int x = v;
#pragma unroll
    for (int o = 1; o < 32; o <<= 1) {
        int y = __shfl_up_sync(0xffffffffu, x, o);
        if (lane >= o) x += y;
    }
    if (lane == 31) wsum[wid] = x;
    __syncthreads();
    if (wid == 0) {
        int w = wsum[lane];
#pragma unroll
        for (int o = 1; o < 32; o <<= 1) {
            int y = __shfl_up_sync(0xffffffffu, w, o);
            if (lane >= o) w += y;
        }
        wsum[lane] = w;
    }
    __syncthreads();
    int incl = x + (wid > 0 ? wsum[wid - 1] : 0);
    if (i < N) g_rowptr[i + 1] = incl;
    if (threadIdx.x == 1023) g_btot[blockIdx.x] = incl;
}
__global__ void k_scan2(int nb) {
    __shared__ int w0tot;
    int lane = threadIdx.x & 31, wid = threadIdx.x >> 5;
    int v = (threadIdx.x < nb) ? g_btot[threadIdx.x] : 0;
    int x = v;
#pragma unroll
    for (int o = 1; o < 32; o <<= 1) {
        int y = __shfl_up_sync(0xffffffffu, x, o);
        if (lane >= o) x += y;
    }
    if (wid == 0 && lane == 31) w0tot = x;
    __syncthreads();
    int excl = x - v + (wid == 1 ? w0tot : 0);
    if (threadIdx.x < nb) g_boff[threadIdx.x] = excl;
    if (threadIdx.x == 0) g_rowptr[0] = 0;
}
__global__ __launch_bounds__(1024)
void k_scan3(int N) {
    int i = blockIdx.x * 1024 + threadIdx.x;
    if (i < N) g_rowptr[i + 1] += g_boff[blockIdx.x];
}

__global__ void k_fill(const void* __restrict__ ei, int E, int N) {
    int i = blockIdx.x * blockDim.x + threadIdx.x;
    if (i < E) {
        int s = edge_at(ei, 0, i, E);
        int d = edge_at(ei, 1, i, E);
        if ((unsigned)s >= (unsigned)N || (unsigned)d >= (unsigned)N) return;
        int pos = g_rowptr[d] + atomicAdd(&g_cnt[d], 1);
        if (pos < MAXE) g_colidx[pos] = s;
    }
}

// ================= stats =================
__global__ void k_zero_stats() { g_stats[threadIdx.x] = 0.f; }

__global__ void k_finstats(const float* __restrict__ gamma,
                           const float* __restrict__ beta, float invN) {
    int c = threadIdx.x;
    float mu = g_stats[c] * invN;
    float var = g_stats[128 + c] * invN - mu * mu;
    float s = gamma[c] * rsqrtf(var + EPSF);
    g_scale[c] = s;
    g_shift[c] = beta[c] - mu * s;
    g_stats[c] = 0.f;
    g_stats[128 + c] = 0.f;
}

// ================= fused dual GEMM: U(h16) = act(X)@Wl, V = act(X)@Wr ============
__global__ __launch_bounds__(256)
void k_gemm(const float4* __restrict__ Xext, int applyBN,
            const float4* __restrict__ Wl4, const float4* __restrict__ Wr4, int N) {
    const float4* __restrict__ X = applyBN ? g_H : Xext;
    __shared__ float  sX[64][33];
    __shared__ float4 sWl[32][32];
    __shared__ float4 sWr[32][32];
    __shared__ float  s_sc[128], s_sh[128];

    const int tid = threadIdx.x;
    const int rg = tid >> 4;
    const int cg = tid & 15;
    const int rowBase = blockIdx.x * 64;

    if (applyBN) {
        if (tid < 128) { s_sc[tid] = g_scale[tid]; s_sh[tid] = g_shift[tid]; }
        __syncthreads();
    }

    float4 aU[4][2], aV[4][2];
    const float4 z4 = make_float4(0.f, 0.f, 0.f, 0.f);
#pragma unroll
    for (int i = 0; i < 4; i++) {
        aU[i][0] = z4; aU[i][1] = z4; aV[i][0] = z4; aV[i][1] = z4;
    }

    for (int k0 = 0; k0 < 32; k0 += 8) {
#pragma unroll
        for (int t = 0; t < 2; t++) {
            int v = tid + t * 256;
            int r = v >> 3, q = v & 7;
            int grow = rowBase + r;
            float4 xv = z4;
            if (grow < N) {
                xv = X[(size_t)grow * 32 + k0 + q];
                if (applyBN) {
                    int cb = (k0 + q) * 4;
                    xv.x = fmaxf(fmaf(xv.x, s_sc[cb + 0], s_sh[cb + 0]), 0.f);
                    xv.y = fmaxf(fmaf(xv.y, s_sc[cb + 1], s_sh[cb + 1]), 0.f);
                    xv.z = fmaxf(fmaf(xv.z, s_sc[cb + 2], s_sh[cb + 2]), 0.f);
                    xv.w = fmaxf(fmaf(xv.w, s_sc[cb + 3], s_sh[cb + 3]), 0.f);
                }
            }
            sX[r][q * 4 + 0] = xv.x;
            sX[r][q * 4 + 1] = xv.y;
            sX[r][q * 4 + 2] = xv.z;
            sX[r][q * 4 + 3] = xv.w;
        }
#pragma unroll
        for (int t = 0; t < 4; t++) {
            int v = tid + t * 256;
            int k = v >> 5, c = v & 31;
            sWl[k][c] = Wl4[(size_t)(k0 * 4 + k) * 32 + c];
            sWr[k][c] = Wr4[(size_t)(k0 * 4 + k) * 32 + c];
        }
        __syncthreads();

#pragma unroll 4
        for (int k = 0; k < 32; k++) {
            float a0 = sX[rg * 4 + 0][k];
            float a1 = sX[rg * 4 + 1][k];
            float a2 = sX[rg * 4 + 2][k];
            float a3 = sX[rg * 4 + 3][k];
            float4 wl0 = sWl[k][cg];
            float4 wl1 = sWl[k][cg + 16];
            float4 wr0 = sWr[k][cg];
            float4 wr1 = sWr[k][cg + 16];
            fma4(aU[0][0], a0, wl0); fma4(aU[0][1], a0, wl1);
            fma4(aU[1][0], a1, wl0); fma4(aU[1][1], a1, wl1);
            fma4(aU[2][0], a2, wl0); fma4(aU[2][1], a2, wl1);
            fma4(aU[3][0], a3, wl0); fma4(aU[3][1], a3, wl1);
            fma4(aV[0][0], a0, wr0); fma4(aV[0][1], a0, wr1);
            fma4(aV[1][0], a1, wr0); fma4(aV[1][1], a1, wr1);
            fma4(aV[2][0], a2, wr0); fma4(aV[2][1], a2, wr1);
            fma4(aV[3][0], a3, wr0); fma4(aV[3][1], a3, wr1);
        }
        __syncthreads();
    }

#pragma unroll
    for (int i = 0; i < 4; i++) {
        int grow = rowBase + rg * 4 + i;
        if (grow < N) {
            size_t base = (size_t)grow * 32;
            g_Uh[base + cg]      = pack_h4(aU[i][0]);   // cols cg*4
            g_Uh[base + 16 + cg] = pack_h4(aU[i][1]);   // cols 64+cg*4
            g_V[base + cg]       = aV[i][0];
            g_V[base + cg + 16]  = aV[i][1];
        }
    }
}

// ================= gather-mean (fp16 U) + bias + BN stats =================
__global__ __launch_bounds__(256)
void k_aggr(const float4* __restrict__ b4, int N) {
    __shared__ float sS[256];
    if (threadIdx.x < 256) sS[threadIdx.x] = 0.f;
    __syncthreads();

    const int lane = threadIdx.x & 31;
    const int gwarp = blockIdx.x * (blockDim.x >> 5) + (threadIdx.x >> 5);
    const int nWarps = gridDim.x * (blockDim.x >> 5);

    // lane's uint2 index within a 32-uint2 row; maps to cols 4j..4j+3.
    // Uh layout: idx cg holds cols 4cg, idx 16+cg holds cols 64+4cg -> for lane<16
    // cols 4*lane; for lane>=16 cols 64+4*(lane-16) = 4*lane. Uniform: cols 4*lane.
    const float4 z4 = make_float4(0.f, 0.f, 0.f, 0.f);
    float4 wSum = z4, wSq = z4;
    const float4 bv = b4[lane];

    for (int node = gwarp; node < N; node += nWarps) {
        int beg = g_rowptr[node];
        int end = g_rowptr[node + 1];
        float4 acc0 = z4, acc1 = z4;
        int e = beg;
        for (; e + 1 < end; e += 2) {
            int s0 = g_colidx[e];
            int s1 = g_colidx[e + 1];
            uint2 u0 = g_Uh[(size_t)s0 * 32 + lane];
            uint2 u1 = g_Uh[(size_t)s1 * 32 + lane];
            addh4(acc0, u0);
            addh4(acc1, u1);
        }
        if (e < end) addh4(acc0, g_Uh[(size_t)g_colidx[e] * 32 + lane]);
        add4(acc0, acc1);

        float di = 1.0f / fmaxf((float)(end - beg), 1.0f);
        float4 v = g_V[(size_t)node * 32 + lane];
        float4 h;
        h.x = fmaf(acc0.x, di, v.x) + bv.x;
        h.y = fmaf(acc0.y, di, v.y) + bv.y;
        h.z = fmaf(acc0.z, di, v.z) + bv.z;
        h.w = fmaf(acc0.w, di, v.w) + bv.w;
        g_H[(size_t)node * 32 + lane] = h;

        add4(wSum, h);
        wSq.x = fmaf(h.x, h.x, wSq.x);
        wSq.y = fmaf(h.y, h.y, wSq.y);
        wSq.z = fmaf(h.z, h.z, wSq.z);
        wSq.w = fmaf(h.w, h.w, wSq.w);
    }

    int c = lane * 4;
    atomicAdd(&sS[c + 0], wSum.x);
    atomicAdd(&sS[c + 1], wSum.y);
    atomicAdd(&sS[c + 2], wSum.z);
    atomicAdd(&sS[c + 3], wSum.w);
    atomicAdd(&sS[128 + c + 0], wSq.x);
    atomicAdd(&sS[128 + c + 1], wSq.y);
    atomicAdd(&sS[128 + c + 2], wSq.z);
    atomicAdd(&sS[128 + c + 3], wSq.w);
    __syncthreads();
    if (threadIdx.x < 256) atomicAdd(&g_stats[threadIdx.x], sS[threadIdx.x]);
}

// ================= final BN + ReLU =================
__global__ void k_epi2(float4* __restrict__ out, int N) {
    __shared__ float sc[128], sh[128];
    if (threadIdx.x < 128) {
        sc[threadIdx.x] = g_scale[threadIdx.x];
        sh[threadIdx.x] = g_shift[threadIdx.x];
    }
    __syncthreads();
    int n4 = N * 32;
    for (int i = blockIdx.x * blockDim.x + threadIdx.x; i < n4;
         i += gridDim.x * blockDim.x) {
        int cq = (i & 31) * 4;
        float4 h = g_H[i];
        float4 o;
        o.x = fmaxf(fmaf(h.x, sc[cq + 0], sh[cq + 0]), 0.f);
        o.y = fmaxf(fmaf(h.y, sc[cq + 1], sh[cq + 1]), 0.f);
        o.z = fmaxf(fmaf(h.z, sc[cq + 2], sh[cq + 2]), 0.f);
        o.w = fmaxf(fmaf(h.w, sc[cq + 3], sh[cq + 3]), 0.f);
        out[i] = o;
    }
}

// ================= launch =================
extern "C" void kernel_launch(void* const* d_in, const int* in_sizes, int n_in,
                              void* d_out, int out_size) {
    const float4* x = (const float4*)d_in[0];
    const void* ei = d_in[1];
    const float4* Wl = (const float4*)d_in[2];
    const float4* Wr = (const float4*)d_in[3];
    const float* b = (const float*)d_in[4];
    const float* gamma = (const float*)d_in[5];
    const float* beta = (const float*)d_in[6];

    int N = in_sizes[0] / 128;
    int E = in_sizes[1] / 2;
    int L = in_sizes[4] / 128;
    float4* out = (float4*)d_out;
    float invN = 1.0f / (float)N;

    int eb = (E + 255) / 256;
    int nb = (N + 255) / 256;
    int nb1 = (N + 1023) / 1024;

    k_detect<<<1, 32>>>((const long long*)ei, N);
    k_zero_cnt<<<nb, 256>>>(N);
    k_hist<<<eb, 256>>>(ei, E, N);
    k_scan1<<<nb1, 1024>>>(N);
    k_scan2<<<1, 64>>>(nb1);
    k_scan3<<<nb1, 1024>>>(N);
    k_zero_cnt<<<nb, 256>>>(N);
    k_fill<<<eb, 256>>>(ei, E, N);
    k_zero_stats<<<1, 256>>>();

    int gemmBlocks = (N + 63) / 64;
    for (int l = 0; l < L; l++) {
        k_gemm<<<gemmBlocks, 256>>>(x, (l == 0) ? 0 : 1,
                                    Wl + (size_t)l * 4096, Wr + (size_t)l * 4096, N);
        k_aggr<<<1184, 256>>>((const float4*)b + (size_t)l * 32, N);
        k_finstats<<<1, 128>>>(gamma + (size_t)l * 128, beta + (size_t)l * 128, invN);
    }
    k_epi2<<<1184, 256>>>(out, N);
}